// round 7
// baseline (speedup 1.0000x reference)
#include <cuda_runtime.h>
#include <cuda_bf16.h>

// out[i] = 0.1 * x[i] * sum_j A[i][j] * (1 - x[j])
// A: [n, n] row-major fp32 -> 1.074 GB streamed once per call at n=16384.
// Pure HBM-bandwidth problem; roofline floor ~165 us at the ~6.3 KB/cyc
// chip LTS/DRAM cap. One CTA per row, 256 threads, 8 CTAs/SM.
//
// Design (frozen pending first measurement):
//  - fused: (1 - x) inline, x L2-resident (64 KB), no scratch, one launch
//  - 8 front-batched LDG.128 per iteration (4 A-stream + 4 x) -> MLP_eff~16,
//    fully hides 577-cyc DRAM latency; binding constraint is chip bandwidth
//  - 4 independent fp32 accumulators; ~40 live regs, comfortably occ 8
//  - #pragma unroll 1 guards against ptxas double-unroll -> spill -> occ drop

__global__ __launch_bounds__(256, 8)
void matvec_kernel(const float* __restrict__ A,
                   const float* __restrict__ x,
                   float* __restrict__ out,
                   int n) {
    const int row = blockIdx.x;
    const float4* __restrict__ Arow =
        reinterpret_cast<const float4*>(A + (size_t)row * (size_t)n);
    const float4* __restrict__ x4 = reinterpret_cast<const float4*>(x);

    const int nv = n >> 2;  // float4 count per row

    float s0 = 0.f, s1 = 0.f, s2 = 0.f, s3 = 0.f;
    int j = threadIdx.x;
    const int stride = blockDim.x;
    #pragma unroll 1
    for (; j + 3 * stride < nv; j += 4 * stride) {
        float4 a0 = __ldg(Arow + j);
        float4 a1 = __ldg(Arow + j + stride);
        float4 a2 = __ldg(Arow + j + 2 * stride);
        float4 a3 = __ldg(Arow + j + 3 * stride);
        float4 b0 = __ldg(x4 + j);
        float4 b1 = __ldg(x4 + j + stride);
        float4 b2 = __ldg(x4 + j + 2 * stride);
        float4 b3 = __ldg(x4 + j + 3 * stride);
        b0.x = 1.0f - b0.x; b0.y = 1.0f - b0.y; b0.z = 1.0f - b0.z; b0.w = 1.0f - b0.w;
        b1.x = 1.0f - b1.x; b1.y = 1.0f - b1.y; b1.z = 1.0f - b1.z; b1.w = 1.0f - b1.w;
        b2.x = 1.0f - b2.x; b2.y = 1.0f - b2.y; b2.z = 1.0f - b2.z; b2.w = 1.0f - b2.w;
        b3.x = 1.0f - b3.x; b3.y = 1.0f - b3.y; b3.z = 1.0f - b3.z; b3.w = 1.0f - b3.w;
        s0 = fmaf(a0.x, b0.x, fmaf(a0.y, b0.y, fmaf(a0.z, b0.z, fmaf(a0.w, b0.w, s0))));
        s1 = fmaf(a1.x, b1.x, fmaf(a1.y, b1.y, fmaf(a1.z, b1.z, fmaf(a1.w, b1.w, s1))));
        s2 = fmaf(a2.x, b2.x, fmaf(a2.y, b2.y, fmaf(a2.z, b2.z, fmaf(a2.w, b2.w, s2))));
        s3 = fmaf(a3.x, b3.x, fmaf(a3.y, b3.y, fmaf(a3.z, b3.z, fmaf(a3.w, b3.w, s3))));
    }
    #pragma unroll 1
    for (; j < nv; j += stride) {
        float4 a = __ldg(Arow + j);
        float4 b = __ldg(x4 + j);
        b.x = 1.0f - b.x; b.y = 1.0f - b.y; b.z = 1.0f - b.z; b.w = 1.0f - b.w;
        s0 = fmaf(a.x, b.x, fmaf(a.y, b.y, fmaf(a.z, b.z, fmaf(a.w, b.w, s0))));
    }
    float s = (s0 + s1) + (s2 + s3);

    // warp reduce
    #pragma unroll
    for (int off = 16; off > 0; off >>= 1)
        s += __shfl_down_sync(0xFFFFFFFFu, s, off);

    __shared__ float warp_sums[8];
    const int lane = threadIdx.x & 31;
    const int wid  = threadIdx.x >> 5;
    if (lane == 0) warp_sums[wid] = s;
    __syncthreads();

    if (wid == 0) {
        s = (lane < (blockDim.x >> 5)) ? warp_sums[lane] : 0.f;
        #pragma unroll
        for (int off = 4; off > 0; off >>= 1)
            s += __shfl_down_sync(0xFFFFFFFFu, s, off);
        if (lane == 0)
            out[row] = 0.1f * x[row] * s;
    }
}

extern "C" void kernel_launch(void* const* d_in, const int* in_sizes, int n_in,
                              void* d_out, int out_size) {
    // metadata order: t, x, A
    const float* x = (const float*)d_in[1];
    const float* A = (const float*)d_in[2];
    float* out = (float*)d_out;
    const int n = in_sizes[1];  // 16384

    matvec_kernel<<<n, 256>>>(A, x, out, n);
}